// round 13
// baseline (speedup 1.0000x reference)
#include <cuda_runtime.h>
#include <cuda_fp16.h>
#include <cstdint>

// ---------------------------------------------------------------------------
// GATv2 collapsed:
//   out[e] = leaky_relu( P[src[e]] + Q[dst[e]] ) . w2 + b2
// Two chained tensor-core GEMMs (tf32 m16n8k8):
//   H  = node_feat @ W_node + b_node              [M,128] fp32 scratch
//   P  = H @ W_a1[0:128,:],  Q = H @ W_a1[128:,:] + b_a1   (NO transpose:
//   W_a1 rows are the input 2C dim, columns the output C dim)
// Layer loop idempotent; edge-hidden path dead. PQ fp16 halves L2 gather bytes.
// ---------------------------------------------------------------------------

#define CH 128
#define MAX_NODES 10240

__device__ __half g_PQh[MAX_NODES * 2 * CH];   // per node: [P(128) | Q(128)] fp16
__device__ float  g_H[MAX_NODES * CH];         // node hidden, fp32

__device__ __forceinline__ unsigned int f32_to_tf32(float f) {
    unsigned int r;
    asm("cvt.rna.tf32.f32 %0, %1;" : "=r"(r) : "f"(f));
    return r;
}

__device__ __forceinline__ void mma_tf32_16x8x8(
    float& d0, float& d1, float& d2, float& d3,
    unsigned int a0, unsigned int a1, unsigned int a2, unsigned int a3,
    unsigned int b0, unsigned int b1) {
    asm volatile(
        "mma.sync.aligned.m16n8k8.row.col.f32.tf32.tf32.f32 "
        "{%0,%1,%2,%3}, {%4,%5,%6,%7}, {%8,%9}, {%0,%1,%2,%3};"
        : "+f"(d0), "+f"(d1), "+f"(d2), "+f"(d3)
        : "r"(a0), "r"(a1), "r"(a2), "r"(a3), "r"(b0), "r"(b1));
}

// ---------------------------------------------------------------------------
// GEMM1: H[M,128] = node_feat[M,K] @ W_node[K,128] + b_node.   K=118.
// Block tile 128x128 (full N), 8 warps (4M x 2N), warp 32x64, tf32 MMA.
// ---------------------------------------------------------------------------
__global__ __launch_bounds__(256) void gemm1_kernel(
    const float* __restrict__ A,        // node_feat [M,K]
    const float* __restrict__ W_node,   // [K,128]
    const float* __restrict__ b_node,   // [128]
    int M, int K) {
    __shared__ unsigned int As[128][20];
    __shared__ unsigned int Bs[16][136];

    int tid  = threadIdx.x;
    int brow = blockIdx.x * 128;

    int w    = tid >> 5;
    int lane = tid & 31;
    int wm   = w & 3;
    int wn   = w >> 2;
    int g    = lane >> 2;
    int tg   = lane & 3;

    float acc[2][8][4];
#pragma unroll
    for (int i = 0; i < 2; i++)
#pragma unroll
        for (int j = 0; j < 8; j++)
#pragma unroll
            for (int c = 0; c < 4; c++) acc[i][j][c] = 0.f;

    for (int k0 = 0; k0 < K; k0 += 16) {
#pragma unroll
        for (int i = 0; i < 8; i++) {
            int id = tid + i * 256;
            int r  = id >> 4;
            int k  = id & 15;
            int m  = brow + r;
            float v = 0.f;
            if (m < M && (k0 + k) < K) v = A[(size_t)m * K + k0 + k];
            As[r][k] = f32_to_tf32(v);
        }
#pragma unroll
        for (int i = 0; i < 8; i++) {
            int id = tid + i * 256;
            int k  = id >> 7;
            int n  = id & 127;
            float v = 0.f;
            if ((k0 + k) < K) v = W_node[(size_t)(k0 + k) * CH + n];
            Bs[k][n] = f32_to_tf32(v);
        }
        __syncthreads();

#pragma unroll
        for (int ks = 0; ks < 2; ks++) {
            int kb = ks * 8;
            unsigned int af[2][4];
#pragma unroll
            for (int mt = 0; mt < 2; mt++) {
                int r0 = wm * 32 + mt * 16;
                af[mt][0] = As[r0 + g][kb + tg];
                af[mt][1] = As[r0 + g + 8][kb + tg];
                af[mt][2] = As[r0 + g][kb + tg + 4];
                af[mt][3] = As[r0 + g + 8][kb + tg + 4];
            }
#pragma unroll
            for (int nt = 0; nt < 8; nt++) {
                int n0 = wn * 64 + nt * 8;
                unsigned int b0 = Bs[kb + tg][n0 + g];
                unsigned int b1 = Bs[kb + tg + 4][n0 + g];
#pragma unroll
                for (int mt = 0; mt < 2; mt++) {
                    mma_tf32_16x8x8(acc[mt][nt][0], acc[mt][nt][1],
                                    acc[mt][nt][2], acc[mt][nt][3],
                                    af[mt][0], af[mt][1], af[mt][2], af[mt][3],
                                    b0, b1);
                }
            }
        }
        __syncthreads();
    }

#pragma unroll
    for (int mt = 0; mt < 2; mt++) {
#pragma unroll
        for (int nt = 0; nt < 8; nt++) {
            int col  = wn * 64 + nt * 8 + tg * 2;
            float b0 = b_node[col];
            float b1 = b_node[col + 1];
            int row0 = brow + wm * 32 + mt * 16 + g;
            int row1 = row0 + 8;
            if (row0 < M) {
                float2 v = make_float2(acc[mt][nt][0] + b0, acc[mt][nt][1] + b1);
                *(float2*)&g_H[(size_t)row0 * CH + col] = v;
            }
            if (row1 < M) {
                float2 v = make_float2(acc[mt][nt][2] + b0, acc[mt][nt][3] + b1);
                *(float2*)&g_H[(size_t)row1 * CH + col] = v;
            }
        }
    }
}

// ---------------------------------------------------------------------------
// GEMM2: PQ[:, half*128 + n] = sum_k H[:,k] * W_a1[half*128 + k][n] (+ b_a1
// on the Q half). B staged straight (coalesced): Bs[k][n] = W_a1[half*CH+k0+k][n].
// ---------------------------------------------------------------------------
__global__ __launch_bounds__(256) void gemm2_kernel(
    const float* __restrict__ W_a1,     // [256,128]
    const float* __restrict__ b_a1,     // [128]
    int M) {
    const int N = 2 * CH;
    __shared__ unsigned int As[128][20];
    __shared__ unsigned int Bs[16][136];

    int tid  = threadIdx.x;
    int brow = blockIdx.x * 128;
    int bcol = blockIdx.y * 128;
    int half = blockIdx.y;              // 0 = P, 1 = Q

    int w    = tid >> 5;
    int lane = tid & 31;
    int wm   = w & 3;
    int wn   = w >> 2;
    int g    = lane >> 2;
    int tg   = lane & 3;

    float acc[2][8][4];
#pragma unroll
    for (int i = 0; i < 2; i++)
#pragma unroll
        for (int j = 0; j < 8; j++)
#pragma unroll
            for (int c = 0; c < 4; c++) acc[i][j][c] = 0.f;

#pragma unroll 1
    for (int k0 = 0; k0 < CH; k0 += 16) {
#pragma unroll
        for (int i = 0; i < 8; i++) {
            int id = tid + i * 256;
            int r  = id >> 4;
            int k  = id & 15;
            int m  = brow + r;
            float v = (m < M) ? g_H[(size_t)m * CH + k0 + k] : 0.f;
            As[r][k] = f32_to_tf32(v);
        }
        // B staging (coalesced, NOT transposed): k runs along W_a1 rows.
#pragma unroll
        for (int i = 0; i < 8; i++) {
            int id = tid + i * 256;
            int k  = id >> 7;            // 0..15
            int n  = id & 127;
            float v = W_a1[(size_t)(half * CH + k0 + k) * CH + n];
            Bs[k][n] = f32_to_tf32(v);
        }
        __syncthreads();

#pragma unroll
        for (int ks = 0; ks < 2; ks++) {
            int kb = ks * 8;
            unsigned int af[2][4];
#pragma unroll
            for (int mt = 0; mt < 2; mt++) {
                int r0 = wm * 32 + mt * 16;
                af[mt][0] = As[r0 + g][kb + tg];
                af[mt][1] = As[r0 + g + 8][kb + tg];
                af[mt][2] = As[r0 + g][kb + tg + 4];
                af[mt][3] = As[r0 + g + 8][kb + tg + 4];
            }
#pragma unroll
            for (int nt = 0; nt < 8; nt++) {
                int n0 = wn * 64 + nt * 8;
                unsigned int b0 = Bs[kb + tg][n0 + g];
                unsigned int b1 = Bs[kb + tg + 4][n0 + g];
#pragma unroll
                for (int mt = 0; mt < 2; mt++) {
                    mma_tf32_16x8x8(acc[mt][nt][0], acc[mt][nt][1],
                                    acc[mt][nt][2], acc[mt][nt][3],
                                    af[mt][0], af[mt][1], af[mt][2], af[mt][3],
                                    b0, b1);
                }
            }
        }
        __syncthreads();
    }

#pragma unroll
    for (int mt = 0; mt < 2; mt++) {
#pragma unroll
        for (int nt = 0; nt < 8; nt++) {
            int nloc = wn * 64 + nt * 8 + tg * 2;
            int col  = bcol + nloc;
            float b0 = half ? b_a1[nloc]     : 0.f;
            float b1 = half ? b_a1[nloc + 1] : 0.f;
            int row0 = brow + wm * 32 + mt * 16 + g;
            int row1 = row0 + 8;
            if (row0 < M) {
                __half2 h = __floats2half2_rn(acc[mt][nt][0] + b0,
                                              acc[mt][nt][1] + b1);
                *(__half2*)&g_PQh[(size_t)row0 * N + col] = h;
            }
            if (row1 < M) {
                __half2 h = __floats2half2_rn(acc[mt][nt][2] + b0,
                                              acc[mt][nt][3] + b1);
                *(__half2*)&g_PQh[(size_t)row1 * N + col] = h;
            }
        }
    }
}

// ---------------------------------------------------------------------------
// Kernel 3 (proven r10): 16 lanes/edge, 8 edges per warp, MLP 8.
// ---------------------------------------------------------------------------
__global__ __launch_bounds__(256) void edge_kernel(
    const int* __restrict__ src, const int* __restrict__ dst,
    const float* __restrict__ W_a2,   // [128]
    const float* __restrict__ b_a2,   // [1]
    float* __restrict__ out, int E) {
    int gwarp = (blockIdx.x * blockDim.x + threadIdx.x) >> 5;
    int lane  = threadIdx.x & 31;
    int sub   = lane & 15;
    int hw    = lane >> 4;

    int eb = gwarp * 8 + hw;

    int  ee[4];
    bool vv[4];
#pragma unroll
    for (int j = 0; j < 4; j++) {
        ee[j] = eb + 2 * j;
        vv[j] = (ee[j] < E);
    }

    int sidx[4], didx[4];
#pragma unroll
    for (int j = 0; j < 4; j++) {
        int ec  = vv[j] ? ee[j] : 0;
        sidx[j] = src[ec];
        didx[j] = dst[ec];
    }

    const uint4* PQ = (const uint4*)g_PQh;
    uint4 pv[4], qv[4];
#pragma unroll
    for (int j = 0; j < 4; j++) {
        pv[j] = PQ[(size_t)sidx[j] * 32 + sub];
        qv[j] = PQ[(size_t)didx[j] * 32 + 16 + sub];
    }

    float4 w0 = ((const float4*)W_a2)[sub * 2];
    float4 w1 = ((const float4*)W_a2)[sub * 2 + 1];
    float wv[8] = {w0.x, w0.y, w0.z, w0.w, w1.x, w1.y, w1.z, w1.w};

    const __half2 slope = __float2half2_rn(0.01f);

    float acc[4] = {0.f, 0.f, 0.f, 0.f};
#pragma unroll
    for (int j = 0; j < 4; j++) {
        const __half2* ph = (const __half2*)&pv[j];
        const __half2* qh = (const __half2*)&qv[j];
#pragma unroll
        for (int i = 0; i < 4; i++) {
            __half2 x = __hadd2(ph[i], qh[i]);
            x = __hmax2(x, __hmul2(x, slope));
            float2 f = __half22float2(x);
            acc[j] = fmaf(f.x, wv[2 * i],     acc[j]);
            acc[j] = fmaf(f.y, wv[2 * i + 1], acc[j]);
        }
    }
#pragma unroll
    for (int off = 8; off; off >>= 1) {
#pragma unroll
        for (int j = 0; j < 4; j++)
            acc[j] += __shfl_xor_sync(0xFFFFFFFFu, acc[j], off);
    }

    if (sub == 0) {
        float b2 = b_a2[0];
#pragma unroll
        for (int j = 0; j < 4; j++)
            if (vv[j]) out[ee[j]] = acc[j] + b2;
    }
}

// ---------------------------------------------------------------------------
extern "C" void kernel_launch(void* const* d_in, const int* in_sizes, int n_in,
                              void* d_out, int out_size) {
    const float* node_feat = (const float*)d_in[0];
    const int*   src       = (const int*)  d_in[2];
    const int*   dst       = (const int*)  d_in[3];
    const float* W_node    = (const float*)d_in[4];
    const float* b_node    = (const float*)d_in[5];
    const float* W_a1      = (const float*)d_in[8];
    const float* b_a1      = (const float*)d_in[9];
    const float* W_a2      = (const float*)d_in[10];
    const float* b_a2      = (const float*)d_in[11];
    float* out = (float*)d_out;

    int E = in_sizes[2];
    int K = in_sizes[4] / CH;        // 118
    int M = in_sizes[0] / K;         // 10000

    {
        dim3 g((M + 127) / 128, 1);
        gemm1_kernel<<<g, 256>>>(node_feat, W_node, b_node, M, K);
    }
    {
        dim3 g((M + 127) / 128, 2);
        gemm2_kernel<<<g, 256>>>(W_a1, b_a1, M);
    }
    {
        int nwarps = (E + 7) / 8;               // 8 edges per warp
        int blocks = (nwarps * 32 + 255) / 256;
        edge_kernel<<<blocks, 256>>>(src, dst, W_a2, b_a2, out, E);
    }
}